// round 1
// baseline (speedup 1.0000x reference)
#include <cuda_runtime.h>
#include <cuda_bf16.h>

// ============================================================================
// SSIM loss, separable Gaussian formulation.
//
// Input:  pred, gt  : (2048, 4096, 3) fp32, HWC. Tile b = row b of the image,
//         viewed as a 64x64x3 block (fully contiguous 49152 B in gmem).
// Per tile, per channel:
//   horizontal 11-tap Gaussian over 5 signals (x, y, x^2, y^2, x*y): 64x64 -> 64x54
//   vertical   11-tap Gaussian:                                      64x54 -> 54x54
//   ssim_map = (2*mu1mu2+C1)(2*sigma12+C2) / ((mu1^2+mu2^2+C1)(sig1+sig2+C2))
// Output: 1 - mean(ssim_map) over 2048*3*54*54 = 17,915,904 values.
// ============================================================================

static constexpr int THREADS = 384;
static constexpr int NBLK    = 2048;
static constexpr float C1 = 1.0e-4f;   // (0.01*L)^2, L = 1 (inputs uniform [0,1))
static constexpr float C2 = 9.0e-4f;   // (0.03*L)^2

// Gaussian taps, sigma = 1.5, ws = 11, normalized (matches reference f64->f32).
__device__ constexpr float G[11] = {
    0.00102840f, 0.00759878f, 0.03600077f, 0.10936042f, 0.21300560f,
    0.26601170f,
    0.21300560f, 0.10936042f, 0.03600077f, 0.00759878f, 0.00102840f
};

struct SmemLayout {
    float xs[64][65];     // pred channel plane (+1 pad col: row stride 65)
    float ys[64][65];     // gt channel plane
    float hb[5][64][54];  // horizontal-pass results for 5 signals
};
static constexpr int SMEM_BYTES = (int)sizeof(SmemLayout);  // 102,400 B

// Deterministic per-tile partial sums (no atomics anywhere).
__device__ float g_part[NBLK];

__global__ __launch_bounds__(THREADS, 2)
void ssim_main(const float* __restrict__ pred, const float* __restrict__ gt)
{
    extern __shared__ unsigned char smem_raw[];
    SmemLayout& s = *reinterpret_cast<SmemLayout*>(smem_raw);

    const int b   = blockIdx.x;
    const int tid = threadIdx.x;
    const float* pb = pred + (size_t)b * 12288;  // 4096 px * 3 ch
    const float* gb = gt   + (size_t)b * 12288;

    float local = 0.0f;

    for (int ch = 0; ch < 3; ++ch) {
        __syncthreads();  // previous iteration fully done with smem

        // ---- load one channel plane (stride-3 gmem; L1 reuses lines across ch)
        for (int i = tid; i < 4096; i += THREADS) {
            const int r = i >> 6, c = i & 63;
            s.xs[r][c] = pb[i * 3 + ch];
            s.ys[r][c] = gb[i * 3 + ch];
        }
        __syncthreads();

        // ---- horizontal pass: 384 tasks = 64 rows x 6 segments of 9 outputs.
        // Stream 19 input pixels, scatter into 9x5 register accumulators.
        {
            const int r  = tid / 6;
            const int c0 = (tid % 6) * 9;
            float a0[9], a1[9], a2[9], a3[9], a4[9];
            #pragma unroll
            for (int o = 0; o < 9; ++o) { a0[o]=0.f; a1[o]=0.f; a2[o]=0.f; a3[o]=0.f; a4[o]=0.f; }

            #pragma unroll
            for (int j = 0; j < 19; ++j) {
                const float x = s.xs[r][c0 + j];
                const float y = s.ys[r][c0 + j];
                const float xx = x * x, yy = y * y, xy = x * y;
                #pragma unroll
                for (int k = 0; k < 11; ++k) {
                    const int o = j - k;            // compile-time pruned
                    if (o >= 0 && o < 9) {
                        const float w = G[k];       // immediate-form FFMA
                        a0[o] = fmaf(w, x,  a0[o]);
                        a1[o] = fmaf(w, y,  a1[o]);
                        a2[o] = fmaf(w, xx, a2[o]);
                        a3[o] = fmaf(w, yy, a3[o]);
                        a4[o] = fmaf(w, xy, a4[o]);
                    }
                }
            }
            #pragma unroll
            for (int o = 0; o < 9; ++o) {
                s.hb[0][r][c0 + o] = a0[o];
                s.hb[1][r][c0 + o] = a1[o];
                s.hb[2][r][c0 + o] = a2[o];
                s.hb[3][r][c0 + o] = a3[o];
                s.hb[4][r][c0 + o] = a4[o];
            }
        }
        __syncthreads();

        // ---- vertical pass + ssim: 324 tasks = 54 cols x 6 segments of 9 rows.
        if (tid < 324) {
            const int c  = tid % 54;          // consecutive threads -> contiguous LDS
            const int r0 = (tid / 54) * 9;
            float a0[9], a1[9], a2[9], a3[9], a4[9];
            #pragma unroll
            for (int o = 0; o < 9; ++o) { a0[o]=0.f; a1[o]=0.f; a2[o]=0.f; a3[o]=0.f; a4[o]=0.f; }

            #pragma unroll
            for (int j = 0; j < 19; ++j) {
                const int rr = r0 + j;
                const float v0 = s.hb[0][rr][c];
                const float v1 = s.hb[1][rr][c];
                const float v2 = s.hb[2][rr][c];
                const float v3 = s.hb[3][rr][c];
                const float v4 = s.hb[4][rr][c];
                #pragma unroll
                for (int k = 0; k < 11; ++k) {
                    const int o = j - k;
                    if (o >= 0 && o < 9) {
                        const float w = G[k];
                        a0[o] = fmaf(w, v0, a0[o]);
                        a1[o] = fmaf(w, v1, a1[o]);
                        a2[o] = fmaf(w, v2, a2[o]);
                        a3[o] = fmaf(w, v3, a3[o]);
                        a4[o] = fmaf(w, v4, a4[o]);
                    }
                }
            }
            #pragma unroll
            for (int o = 0; o < 9; ++o) {
                const float mu1 = a0[o], mu2 = a1[o];
                const float mu1s = mu1 * mu1;
                const float mu2s = mu2 * mu2;
                const float m12  = mu1 * mu2;
                const float s1   = a2[o] - mu1s;
                const float s2   = a3[o] - mu2s;
                const float s12  = a4[o] - m12;
                const float v1t  = fmaf(2.0f, s12, C2);
                const float v2t  = s1 + s2 + C2;
                const float num  = fmaf(2.0f, m12, C1) * v1t;
                const float den  = (mu1s + mu2s + C1) * v2t;
                local += __fdividef(num, den);
            }
        }
    }

    // ---- fixed-order block reduction -> deterministic per-tile partial
    __syncthreads();
    #pragma unroll
    for (int off = 16; off > 0; off >>= 1)
        local += __shfl_down_sync(0xffffffffu, local, off);

    __shared__ float red[THREADS / 32];
    if ((tid & 31) == 0) red[tid >> 5] = local;
    __syncthreads();
    if (tid == 0) {
        float sum = 0.0f;
        #pragma unroll
        for (int w = 0; w < THREADS / 32; ++w) sum += red[w];
        g_part[b] = sum;
    }
}

__global__ void ssim_finalize(float* __restrict__ out)
{
    const int tid = threadIdx.x;  // 256 threads
    float sum = 0.0f;
    for (int i = tid; i < NBLK; i += 256) sum += g_part[i];  // fixed order
    #pragma unroll
    for (int off = 16; off > 0; off >>= 1)
        sum += __shfl_down_sync(0xffffffffu, sum, off);

    __shared__ float red[8];
    if ((tid & 31) == 0) red[tid >> 5] = sum;
    __syncthreads();
    if (tid == 0) {
        float t = 0.0f;
        #pragma unroll
        for (int w = 0; w < 8; ++w) t += red[w];
        // N = 2048 * 3 * 54 * 54 = 17,915,904
        out[0] = 1.0f - t * (1.0f / 17915904.0f);
    }
}

extern "C" void kernel_launch(void* const* d_in, const int* in_sizes, int n_in,
                              void* d_out, int out_size)
{
    const float* pred = (const float*)d_in[0];
    const float* gt   = (const float*)d_in[1];
    float* out        = (float*)d_out;

    // >48KB dynamic smem opt-in (not a stream op; capture-safe).
    cudaFuncSetAttribute(ssim_main, cudaFuncAttributeMaxDynamicSharedMemorySize,
                         SMEM_BYTES);

    ssim_main<<<NBLK, THREADS, SMEM_BYTES>>>(pred, gt);
    ssim_finalize<<<1, 256>>>(out);
}

// round 2
// speedup vs baseline: 1.3581x; 1.3581x over previous
#include <cuda_runtime.h>
#include <cuda_bf16.h>

// ============================================================================
// SSIM loss, separable Gaussian, 4-signal (u=x+y, v=x-y) f32x2-packed form.
//
// Per tile (64x64x3, contiguous 49152 B) per channel:
//   signals u, v, u^2, v^2 -> horizontal 11-tap (64x64 -> 64x54, f32x2 pairs)
//                           -> vertical   11-tap (64x54 -> 54x54)
//   p=conv(u)=mu1+mu2, q=conv(v)=mu1-mu2, Su=conv(u^2), Sv=conv(v^2)
//   A=2*mu1*mu2=(p^2-q^2)/2, B=mu1^2+mu2^2=(p^2+q^2)/2
//   num=(A+C1)*((Su-Sv)/2 - A + C2),  den=(B+C1)*((Su+Sv)/2 - B + C2)
// Output: 1 - mean over 2048*3*54*54 values. Single fused kernel.
// ============================================================================

static constexpr int THREADS = 384;
static constexpr int NBLK    = 2048;
static constexpr float C1 = 1.0e-4f;   // (0.01*L)^2, L = 1
static constexpr float C2 = 9.0e-4f;

__device__ constexpr float G[11] = {
    0.00102840f, 0.00759878f, 0.03600077f, 0.10936042f, 0.21300560f,
    0.26601170f,
    0.21300560f, 0.10936042f, 0.03600077f, 0.00759878f, 0.00102840f
};

typedef unsigned long long u64;

__device__ __forceinline__ u64 pack2(float a, float b) {
    u64 r;
    asm("mov.b64 %0, {%1, %2};" : "=l"(r) : "f"(a), "f"(b));
    return r;
}
__device__ __forceinline__ void unpack2(u64 p, float& a, float& b) {
    asm("mov.b64 {%0, %1}, %2;" : "=f"(a), "=f"(b) : "l"(p));
}
__device__ __forceinline__ u64 fma2(u64 a, u64 b, u64 c) {
    u64 d;
    asm("fma.rn.f32x2 %0, %1, %2, %3;" : "=l"(d) : "l"(a), "l"(b), "l"(c));
    return d;
}
__device__ __forceinline__ u64 mul2(u64 a, u64 b) {
    u64 d;
    asm("mul.rn.f32x2 %0, %1, %2;" : "=l"(d) : "l"(a), "l"(b));
    return d;
}

struct SmemLayout {
    float2 plane[64][65];   // (u, v) per pixel, +1 pad col     : 33,280 B
    float4 hb[64][54];      // (p, q, Su, Sv) after h-pass      : 55,296 B
};
static constexpr int SMEM_BYTES = (int)sizeof(SmemLayout);  // 88,576 B

__device__ float        g_part[NBLK];
__device__ unsigned int g_count = 0;

__global__ __launch_bounds__(THREADS, 2)
void ssim_main(const float* __restrict__ pred, const float* __restrict__ gt,
               float* __restrict__ out)
{
    extern __shared__ unsigned char smem_raw[];
    SmemLayout& s = *reinterpret_cast<SmemLayout*>(smem_raw);

    const int b   = blockIdx.x;
    const int tid = threadIdx.x;
    const float* pb = pred + (size_t)b * 12288;
    const float* gb = gt   + (size_t)b * 12288;

    // packed weights (constant-folded in the unrolled loops)
    u64 W[11];
    #pragma unroll
    for (int k = 0; k < 11; ++k) W[k] = pack2(G[k], G[k]);

    float local = 0.0f;

    for (int ch = 0; ch < 3; ++ch) {
        __syncthreads();  // prior v-pass done with hb; plane free since earlier

        // ---- load channel plane, form (u, v) = (x+y, x-y)
        for (int i = tid; i < 4096; i += THREADS) {
            const float x = pb[i * 3 + ch];
            const float y = gb[i * 3 + ch];
            s.plane[i >> 6][i & 63] = make_float2(x + y, x - y);
        }
        __syncthreads();

        // ---- horizontal pass: 64 rows x 6 segments of 9 outputs
        {
            const int r  = tid / 6;
            const int c0 = (tid % 6) * 9;
            const u64* prow = reinterpret_cast<const u64*>(&s.plane[r][0]);

            u64 auv[9], asq[9];
            #pragma unroll
            for (int o = 0; o < 9; ++o) { auv[o] = 0ull; asq[o] = 0ull; }

            #pragma unroll
            for (int j = 0; j < 19; ++j) {
                const u64 uv = prow[c0 + j];        // LDS.64
                const u64 sq = mul2(uv, uv);
                #pragma unroll
                for (int k = 0; k < 11; ++k) {
                    const int o = j - k;            // compile-time pruned
                    if (o >= 0 && o < 9) {
                        auv[o] = fma2(W[k], uv, auv[o]);
                        asq[o] = fma2(W[k], sq, asq[o]);
                    }
                }
            }
            #pragma unroll
            for (int o = 0; o < 9; ++o) {
                float p, q, su, sv;
                unpack2(auv[o], p, q);
                unpack2(asq[o], su, sv);
                s.hb[r][c0 + o] = make_float4(p, q, su, sv);  // STS.128
            }
        }
        __syncthreads();

        // ---- vertical pass + ssim: 54 cols x 6 segments of 9 rows
        if (tid < 324) {
            const int c  = tid % 54;
            const int r0 = (tid / 54) * 9;

            u64 auv[9], asq[9];
            #pragma unroll
            for (int o = 0; o < 9; ++o) { auv[o] = 0ull; asq[o] = 0ull; }

            #pragma unroll
            for (int j = 0; j < 19; ++j) {
                const ulonglong2 t =
                    *reinterpret_cast<const ulonglong2*>(&s.hb[r0 + j][c]); // LDS.128
                #pragma unroll
                for (int k = 0; k < 11; ++k) {
                    const int o = j - k;
                    if (o >= 0 && o < 9) {
                        auv[o] = fma2(W[k], t.x, auv[o]);
                        asq[o] = fma2(W[k], t.y, asq[o]);
                    }
                }
            }
            #pragma unroll
            for (int o = 0; o < 9; ++o) {
                float p, q, su, sv;
                unpack2(auv[o], p, q);
                unpack2(asq[o], su, sv);
                const float P = p * p, Q = q * q;
                const float A = 0.5f * (P - Q);           // 2*mu1*mu2
                const float B = 0.5f * (P + Q);           // mu1^2+mu2^2
                const float num = (A + C1) * (fmaf(0.5f, su - sv, C2) - A);
                const float den = (B + C1) * (fmaf(0.5f, su + sv, C2) - B);
                local += __fdividef(num, den);
            }
        }
    }

    // ---- fixed-order block reduction -> per-tile partial
    __syncthreads();
    #pragma unroll
    for (int off = 16; off > 0; off >>= 1)
        local += __shfl_down_sync(0xffffffffu, local, off);

    __shared__ float red[THREADS / 32];
    __shared__ unsigned int ticket;
    if ((tid & 31) == 0) red[tid >> 5] = local;
    __syncthreads();
    if (tid == 0) {
        float sum = 0.0f;
        #pragma unroll
        for (int w = 0; w < THREADS / 32; ++w) sum += red[w];
        g_part[b] = sum;
        __threadfence();
        ticket = atomicAdd(&g_count, 1u);
    }
    __syncthreads();

    // ---- last block performs the deterministic global reduction
    if (ticket == NBLK - 1) {
        float sum = 0.0f;
        for (int i = tid; i < NBLK; i += THREADS) sum += g_part[i];  // fixed order
        #pragma unroll
        for (int off = 16; off > 0; off >>= 1)
            sum += __shfl_down_sync(0xffffffffu, sum, off);
        if ((tid & 31) == 0) red[tid >> 5] = sum;
        __syncthreads();
        if (tid == 0) {
            float t = 0.0f;
            #pragma unroll
            for (int w = 0; w < THREADS / 32; ++w) t += red[w];
            // N = 2048 * 3 * 54 * 54 = 17,915,904
            out[0] = 1.0f - t * (1.0f / 17915904.0f);
            g_count = 0;   // reset for next graph replay
        }
    }
}

extern "C" void kernel_launch(void* const* d_in, const int* in_sizes, int n_in,
                              void* d_out, int out_size)
{
    const float* pred = (const float*)d_in[0];
    const float* gt   = (const float*)d_in[1];
    float* out        = (float*)d_out;

    cudaFuncSetAttribute(ssim_main, cudaFuncAttributeMaxDynamicSharedMemorySize,
                         SMEM_BYTES);
    ssim_main<<<NBLK, THREADS, SMEM_BYTES>>>(pred, gt, out);
}